// round 4
// baseline (speedup 1.0000x reference)
#include <cuda_runtime.h>
#include <cuda_bf16.h>
#include <cstdint>

// ---------------- problem constants ----------------
#define B_ROWS 16384
#define DIN 512
#define DOUT 512
#define NE 8
#define GCOLS 2

// ---------------- GEMM tiling ----------------
#define TM 128
#define TN 128
#define TK 32
#define NSTAGE (DIN / TK)          // 16
#define MAXT (B_ROWS / TM + NE)    // 136

#define SA 40    // A smem row stride (elems): 80B, conflict-free ldmatrix (5 mod 8 granules)
#define SB 136   // B smem row stride (elems): 272B (17 mod 8 = 1)

// per-buffer smem offsets (bytes)
#define AHI 0
#define ALO (TM * SA * 2)                    // 10240
#define BHI (2 * TM * SA * 2)                // 20480
#define BLO (2 * TM * SA * 2 + TK * SB * 2)  // 29184
#define BUF_BYTES (2 * TM * SA * 2 + 2 * TK * SB * 2)  // 37888
#define OFF_BUF 512
#define GEMM_SMEM (OFF_BUF + 2 * BUF_BYTES)  // 76288 -> 2 CTAs/SM fit

// ---------------- device scratch ----------------
__device__ int g_counts[NE];
__device__ int g_offsets[NE];
__device__ int g_fill[NE];
__device__ int g_rowidx[B_ROWS];
__device__ int g_tile_expert[MAXT];
__device__ int g_tile_rowbase[MAXT];
__device__ int g_tile_rows[MAXT];

__device__ __align__(16) __nv_bfloat16 g_xhi[B_ROWS * DIN];
__device__ __align__(16) __nv_bfloat16 g_xlo[B_ROWS * DIN];
__device__ __align__(16) __nv_bfloat16 g_whi[NE * DIN * DOUT];   // [e][k][n]
__device__ __align__(16) __nv_bfloat16 g_wlo[NE * DIN * DOUT];

// ---------------- helpers ----------------
__device__ __forceinline__ uint32_t smem_u32(const void* p) {
    uint32_t a;
    asm("{ .reg .u64 t; cvta.to.shared.u64 t, %1; cvt.u32.u64 %0, t; }" : "=r"(a) : "l"(p));
    return a;
}
__device__ __forceinline__ void ldsm_x4(uint32_t* r, uint32_t addr) {
    asm volatile("ldmatrix.sync.aligned.m8n8.x4.shared.b16 {%0,%1,%2,%3}, [%4];"
                 : "=r"(r[0]), "=r"(r[1]), "=r"(r[2]), "=r"(r[3]) : "r"(addr));
}
__device__ __forceinline__ void ldsm_x4_t(uint32_t* r, uint32_t addr) {
    asm volatile("ldmatrix.sync.aligned.m8n8.x4.trans.shared.b16 {%0,%1,%2,%3}, [%4];"
                 : "=r"(r[0]), "=r"(r[1]), "=r"(r[2]), "=r"(r[3]) : "r"(addr));
}
__device__ __forceinline__ void mma_bf16(float* c, const uint32_t* a, const uint32_t* b) {
    asm volatile(
        "mma.sync.aligned.m16n8k16.row.col.f32.bf16.bf16.f32 "
        "{%0,%1,%2,%3}, {%4,%5,%6,%7}, {%8,%9}, {%0,%1,%2,%3};"
        : "+f"(c[0]), "+f"(c[1]), "+f"(c[2]), "+f"(c[3])
        : "r"(a[0]), "r"(a[1]), "r"(a[2]), "r"(a[3]), "r"(b[0]), "r"(b[1]));
}
#define CP_ASYNC16(saddr, gaddr) \
    asm volatile("cp.async.cg.shared.global [%0], [%1], 16;" :: "r"(saddr), "l"(gaddr))
#define CP_COMMIT() asm volatile("cp.async.commit_group;")
#define CP_WAIT(n)  asm volatile("cp.async.wait_group %0;" :: "n"(n) : "memory")

__device__ __forceinline__ void split2(float a, float b, uint32_t& h, uint32_t& l) {
    __nv_bfloat162 hv = __floats2bfloat162_rn(a, b);
    float2 hf = __bfloat1622float2(hv);
    __nv_bfloat162 lv = __floats2bfloat162_rn(a - hf.x, b - hf.y);
    h = *reinterpret_cast<uint32_t*>(&hv);
    l = *reinterpret_cast<uint32_t*>(&lv);
}

// ---------------- bucketing ----------------
__global__ void reset_kernel() {
    int t = threadIdx.x;
    if (t < NE) { g_counts[t] = 0; g_fill[t] = 0; }
}

__global__ void hist_kernel(const int* __restrict__ groups) {
    __shared__ int s[NE];
    if (threadIdx.x < NE) s[threadIdx.x] = 0;
    __syncthreads();
    for (int b = blockIdx.x * blockDim.x + threadIdx.x; b < B_ROWS;
         b += gridDim.x * blockDim.x)
        atomicAdd(&s[groups[b * GCOLS]], 1);
    __syncthreads();
    if (threadIdx.x < NE) atomicAdd(&g_counts[threadIdx.x], s[threadIdx.x]);
}

__global__ void scan_kernel() {
    if (threadIdx.x == 0) {
        int total = 0, t = 0;
        for (int e = 0; e < NE; e++) {
            g_offsets[e] = total;
            int cnt = g_counts[e];
            for (int s = 0; s < cnt; s += TM) {
                g_tile_expert[t]  = e;
                g_tile_rowbase[t] = total + s;
                g_tile_rows[t]    = (cnt - s < TM) ? (cnt - s) : TM;
                t++;
            }
            total += cnt;
        }
        for (; t < MAXT; t++) g_tile_expert[t] = -1;
    }
}

__global__ void scatter_kernel(const int* __restrict__ groups) {
    int b = blockIdx.x * blockDim.x + threadIdx.x;
    int e = groups[b * GCOLS];
    int lane = threadIdx.x & 31;
    unsigned mask = __match_any_sync(0xffffffffu, e);
    int leader = __ffs(mask) - 1;
    int prefix = __popc(mask & ((1u << lane) - 1));
    int base = 0;
    if (lane == leader) base = atomicAdd(&g_fill[e], __popc(mask));
    base = __shfl_sync(0xffffffffu, base, leader);
    g_rowidx[g_offsets[e] + base + prefix] = b;
}

// ---------------- precision-split prep ----------------
__global__ void split_x_kernel(const float* __restrict__ x) {
    int i = blockIdx.x * blockDim.x + threadIdx.x;  // float4 index
    float4 v = ((const float4*)x)[i];
    uint2 H, L;
    split2(v.x, v.y, H.x, L.x);
    split2(v.z, v.w, H.y, L.y);
    ((uint2*)g_xhi)[i] = H;
    ((uint2*)g_xlo)[i] = L;
}

__global__ void split_w_kernel(const float* __restrict__ W) {
    int i = blockIdx.x * blockDim.x + threadIdx.x;  // float4 index
    float4 v = ((const float4*)W)[i];
    uint2 H, L;
    split2(v.x, v.y, H.x, L.x);
    split2(v.z, v.w, H.y, L.y);
    ((uint2*)g_whi)[i] = H;
    ((uint2*)g_wlo)[i] = L;
}

// ---------------- grouped GEMM: cp.async pipeline + mma.sync 3-term ----------------
__global__ __launch_bounds__(256, 2)
void gemm_mma(const float* __restrict__ bias, float* __restrict__ out) {
    const int tile = blockIdx.x;
    const int e = g_tile_expert[tile];
    if (e < 0) return;
    const int rowbase = g_tile_rowbase[tile];
    const int rows    = g_tile_rows[tile];
    const int n0      = blockIdx.y * TN;

    extern __shared__ char sm[];
    int* srows = (int*)sm;
    const uint32_t smu = smem_u32(sm);

    const int tid  = threadIdx.x;
    const int lane = tid & 31;
    const int wid  = tid >> 5;

    if (tid < TM) srows[tid] = (tid < rows) ? g_rowidx[rowbase + tid] : -1;
    __syncthreads();

    // ---- cp.async slots: 4 A-chunks + 4 B-chunks per thread, 16B each ----
    // A: 2 tensors x 128 rows x 4 sectors
    const __nv_bfloat16* ag[4]; uint32_t asw[4];
#pragma unroll
    for (int t = 0; t < 4; t++) {
        int c = tid + t * 256;
        int tensor = c >> 9;
        int m   = (c >> 2) & 127;
        int sec = c & 3;
        int gr = srows[m]; if (gr < 0) gr = 0;
        ag[t]  = (tensor ? g_xlo : g_xhi) + (size_t)gr * DIN + sec * 8;
        asw[t] = OFF_BUF + (tensor ? ALO : AHI) + m * (SA * 2) + sec * 16;
    }
    // B: 2 tensors x 32 k-rows x 16 sectors
    const __nv_bfloat16* bg[4]; uint32_t bsw[4];
#pragma unroll
    for (int t = 0; t < 4; t++) {
        int c = tid + t * 256;
        int tensor = c >> 9;
        int k   = (c >> 4) & 31;
        int sec = c & 15;
        bg[t]  = (tensor ? g_wlo : g_whi)
               + ((size_t)e * DIN + k) * DOUT + n0 + sec * 8;
        bsw[t] = OFF_BUF + (tensor ? BLO : BHI) + k * (SB * 2) + sec * 16;
    }

    // ---- warp compute coords ----
    const int m0w = (wid >> 1) * 32;
    const int n0w = (wid & 1) * 64;
    const int lr = (lane & 7) + ((lane >> 3) & 1) * 8;
    const int lc = (lane >> 4) * 8;
    const int a_lm_base = ((m0w + lr) * SA + lc) * 2;
    const int b_lm_base = (lr * SB + n0w + lc) * 2;

    float c[2][8][4];
#pragma unroll
    for (int mt = 0; mt < 2; mt++)
#pragma unroll
        for (int nt = 0; nt < 8; nt++)
#pragma unroll
            for (int j = 0; j < 4; j++) c[mt][nt][j] = 0.f;

    // ---- prefetch stages 0 and 1 ----
#pragma unroll
    for (int s = 0; s < 2; s++) {
        const uint32_t bo = smu + s * BUF_BYTES;
        const int ka = s * TK;            // A k-offset (elems)
        const size_t kb = (size_t)(s * TK) * DOUT;  // B row offset (elems)
#pragma unroll
        for (int t = 0; t < 4; t++) CP_ASYNC16(bo + asw[t], ag[t] + ka);
#pragma unroll
        for (int t = 0; t < 4; t++) CP_ASYNC16(bo + bsw[t], bg[t] + kb);
        CP_COMMIT();
    }

    for (int kt = 0; kt < NSTAGE; kt++) {
        if (kt < NSTAGE - 1) CP_WAIT(1); else CP_WAIT(0);
        __syncthreads();

        const int buf = kt & 1;
        const uint32_t bb = smu + OFF_BUF + buf * BUF_BYTES;

#pragma unroll
        for (int ks = 0; ks < 2; ks++) {
            const int kso = ks * 16;
            uint32_t ah[2][4], al[2][4];
#pragma unroll
            for (int mt = 0; mt < 2; mt++) {
                uint32_t ao = bb + a_lm_base + (mt * 16 * SA + kso) * 2;
                ldsm_x4(ah[mt], ao + AHI);
                ldsm_x4(al[mt], ao + ALO);
            }
            uint32_t bh[4][4], bl[4][4];
#pragma unroll
            for (int p = 0; p < 4; p++) {
                uint32_t bo = bb + b_lm_base + (kso * SB + p * 16) * 2;
                ldsm_x4_t(bh[p], bo + BHI);
                ldsm_x4_t(bl[p], bo + BLO);
            }
#pragma unroll
            for (int mt = 0; mt < 2; mt++)
#pragma unroll
                for (int p = 0; p < 4; p++) {
                    mma_bf16(c[mt][2 * p],     ah[mt], &bh[p][0]);
                    mma_bf16(c[mt][2 * p],     al[mt], &bh[p][0]);
                    mma_bf16(c[mt][2 * p],     ah[mt], &bl[p][0]);
                    mma_bf16(c[mt][2 * p + 1], ah[mt], &bh[p][2]);
                    mma_bf16(c[mt][2 * p + 1], al[mt], &bh[p][2]);
                    mma_bf16(c[mt][2 * p + 1], ah[mt], &bl[p][2]);
                }
        }

        __syncthreads();   // all warps done with buf before refill

        if (kt + 2 < NSTAGE) {
            const uint32_t bo = smu + buf * BUF_BYTES;
            const int ka = (kt + 2) * TK;
            const size_t kb = (size_t)((kt + 2) * TK) * DOUT;
#pragma unroll
            for (int t = 0; t < 4; t++) CP_ASYNC16(bo + asw[t], ag[t] + ka);
#pragma unroll
            for (int t = 0; t < 4; t++) CP_ASYNC16(bo + bsw[t], bg[t] + kb);
            CP_COMMIT();
        }
    }

    // ---- epilogue: bias + scattered stores ----
    const int rl = lane >> 2;
    const int cl = (lane & 3) * 2;
#pragma unroll
    for (int mt = 0; mt < 2; mt++) {
        const int lm0 = m0w + mt * 16 + rl;
        const int r0 = srows[lm0];
        const int r1 = srows[lm0 + 8];
#pragma unroll
        for (int nt = 0; nt < 8; nt++) {
            const int gcol = n0 + n0w + nt * 8 + cl;
            const float2 bv2 = *(const float2*)(bias + e * DOUT + gcol);
            if (r0 >= 0) {
                float2 v = make_float2(c[mt][nt][0] + bv2.x, c[mt][nt][1] + bv2.y);
                *(float2*)(out + (size_t)r0 * DOUT + gcol) = v;
            }
            if (r1 >= 0) {
                float2 v = make_float2(c[mt][nt][2] + bv2.x, c[mt][nt][3] + bv2.y);
                *(float2*)(out + (size_t)r1 * DOUT + gcol) = v;
            }
        }
    }
}

// ---------------- launch ----------------
extern "C" void kernel_launch(void* const* d_in, const int* in_sizes, int n_in,
                              void* d_out, int out_size) {
    const float* x      = (const float*)d_in[0];
    const int*   groups = (const int*)d_in[1];
    const float* W      = (const float*)d_in[2];
    const float* bias   = (const float*)d_in[3];
    float*       out    = (float*)d_out;

    cudaFuncSetAttribute(gemm_mma, cudaFuncAttributeMaxDynamicSharedMemorySize, GEMM_SMEM);

    reset_kernel<<<1, 32>>>();
    hist_kernel<<<64, 256>>>(groups);
    scan_kernel<<<1, 32>>>();
    scatter_kernel<<<B_ROWS / 256, 256>>>(groups);
    split_x_kernel<<<B_ROWS * DIN / 4 / 256, 256>>>(x);
    split_w_kernel<<<NE * DIN * DOUT / 4 / 256, 256>>>(W);

    dim3 grid(MAXT, DOUT / TN);
    gemm_mma<<<grid, 256, GEMM_SMEM>>>(bias, out);
}

// round 5
// speedup vs baseline: 1.3509x; 1.3509x over previous
#include <cuda_runtime.h>
#include <cuda_fp16.h>
#include <cstdint>

// ---------------- problem constants ----------------
#define B_ROWS 16384
#define DIN 512
#define DOUT 512
#define NE 8
#define GCOLS 2

// ---------------- GEMM tiling ----------------
#define TM 128
#define TN 128
#define TK 32
#define NSTAGE (DIN / TK)          // 16
#define MAXT (B_ROWS / TM + NE)    // 136

#define SA 40    // A smem row stride (halves): 80B, conflict-free ldmatrix
#define SB 136   // B smem row stride (halves): 272B

// per-buffer smem offsets (bytes): A (single fp16) | B_hi | B_lo
#define AHI 0
#define BHI (TM * SA * 2)                    // 10240
#define BLO (TM * SA * 2 + TK * SB * 2)      // 18944
#define BUF_BYTES (TM * SA * 2 + 2 * TK * SB * 2)  // 27648
#define OFF_BUF 512
#define GEMM_SMEM (OFF_BUF + 2 * BUF_BYTES)  // 55808 -> 2 CTAs/SM

// ---------------- device scratch ----------------
__device__ int g_counts[NE];
__device__ int g_offsets[NE];
__device__ int g_fill[NE];
__device__ int g_rowidx[B_ROWS];
__device__ int g_tile_expert[MAXT];
__device__ int g_tile_rowbase[MAXT];
__device__ int g_tile_rows[MAXT];

__device__ __align__(16) __half g_xh[B_ROWS * DIN];       // 16MB, x in fp16
__device__ __align__(16) __half g_whh[NE * DIN * DOUT];   // 4MB, W hi [e][k][n]
__device__ __align__(16) __half g_whl[NE * DIN * DOUT];   // 4MB, W residual

// ---------------- helpers ----------------
__device__ __forceinline__ uint32_t smem_u32(const void* p) {
    uint32_t a;
    asm("{ .reg .u64 t; cvta.to.shared.u64 t, %1; cvt.u32.u64 %0, t; }" : "=r"(a) : "l"(p));
    return a;
}
__device__ __forceinline__ void ldsm_x4(uint32_t* r, uint32_t addr) {
    asm volatile("ldmatrix.sync.aligned.m8n8.x4.shared.b16 {%0,%1,%2,%3}, [%4];"
                 : "=r"(r[0]), "=r"(r[1]), "=r"(r[2]), "=r"(r[3]) : "r"(addr));
}
__device__ __forceinline__ void ldsm_x4_t(uint32_t* r, uint32_t addr) {
    asm volatile("ldmatrix.sync.aligned.m8n8.x4.trans.shared.b16 {%0,%1,%2,%3}, [%4];"
                 : "=r"(r[0]), "=r"(r[1]), "=r"(r[2]), "=r"(r[3]) : "r"(addr));
}
__device__ __forceinline__ void mma_f16(float* c, const uint32_t* a, const uint32_t* b) {
    asm volatile(
        "mma.sync.aligned.m16n8k16.row.col.f32.f16.f16.f32 "
        "{%0,%1,%2,%3}, {%4,%5,%6,%7}, {%8,%9}, {%0,%1,%2,%3};"
        : "+f"(c[0]), "+f"(c[1]), "+f"(c[2]), "+f"(c[3])
        : "r"(a[0]), "r"(a[1]), "r"(a[2]), "r"(a[3]), "r"(b[0]), "r"(b[1]));
}
#define CP_ASYNC16(saddr, gaddr) \
    asm volatile("cp.async.cg.shared.global [%0], [%1], 16;" :: "r"(saddr), "l"(gaddr))
#define CP_COMMIT() asm volatile("cp.async.commit_group;")
#define CP_WAIT(n)  asm volatile("cp.async.wait_group %0;" :: "n"(n) : "memory")

// ---------------- bucketing ----------------
__global__ void reset_kernel() {
    int t = threadIdx.x;
    if (t < NE) { g_counts[t] = 0; g_fill[t] = 0; }
}

__global__ void hist_kernel(const int* __restrict__ groups) {
    __shared__ int s[NE];
    if (threadIdx.x < NE) s[threadIdx.x] = 0;
    __syncthreads();
    for (int b = blockIdx.x * blockDim.x + threadIdx.x; b < B_ROWS;
         b += gridDim.x * blockDim.x)
        atomicAdd(&s[groups[b * GCOLS]], 1);
    __syncthreads();
    if (threadIdx.x < NE) atomicAdd(&g_counts[threadIdx.x], s[threadIdx.x]);
}

__global__ void scan_kernel() {
    if (threadIdx.x == 0) {
        int total = 0, t = 0;
        for (int e = 0; e < NE; e++) {
            g_offsets[e] = total;
            int cnt = g_counts[e];
            for (int s = 0; s < cnt; s += TM) {
                g_tile_expert[t]  = e;
                g_tile_rowbase[t] = total + s;
                g_tile_rows[t]    = (cnt - s < TM) ? (cnt - s) : TM;
                t++;
            }
            total += cnt;
        }
        for (; t < MAXT; t++) g_tile_expert[t] = -1;
    }
}

__global__ void scatter_kernel(const int* __restrict__ groups) {
    int b = blockIdx.x * blockDim.x + threadIdx.x;
    int e = groups[b * GCOLS];
    int lane = threadIdx.x & 31;
    unsigned mask = __match_any_sync(0xffffffffu, e);
    int leader = __ffs(mask) - 1;
    int prefix = __popc(mask & ((1u << lane) - 1));
    int base = 0;
    if (lane == leader) base = atomicAdd(&g_fill[e], __popc(mask));
    base = __shfl_sync(0xffffffffu, base, leader);
    g_rowidx[g_offsets[e] + base + prefix] = b;
}

// ---------------- fused prep: x -> fp16, W -> fp16 hi+lo ----------------
#define XBLOCKS (B_ROWS * DIN / 4 / 256)       // 8192
#define WBLOCKS (NE * DIN * DOUT / 4 / 256)    // 2048
__global__ void split_kernel(const float* __restrict__ x, const float* __restrict__ W) {
    int bid = blockIdx.x;
    if (bid < XBLOCKS) {
        int i = bid * blockDim.x + threadIdx.x;   // float4 index
        float4 v = ((const float4*)x)[i];
        __half2 h0 = __floats2half2_rn(v.x, v.y);
        __half2 h1 = __floats2half2_rn(v.z, v.w);
        uint2 H = make_uint2(*(uint32_t*)&h0, *(uint32_t*)&h1);
        ((uint2*)g_xh)[i] = H;
    } else {
        int i = (bid - XBLOCKS) * blockDim.x + threadIdx.x;
        float4 v = ((const float4*)W)[i];
        __half2 h0 = __floats2half2_rn(v.x, v.y);
        __half2 h1 = __floats2half2_rn(v.z, v.w);
        float2 f0 = __half22float2(h0);
        float2 f1 = __half22float2(h1);
        __half2 l0 = __floats2half2_rn(v.x - f0.x, v.y - f0.y);
        __half2 l1 = __floats2half2_rn(v.z - f1.x, v.w - f1.y);
        ((uint2*)g_whh)[i] = make_uint2(*(uint32_t*)&h0, *(uint32_t*)&h1);
        ((uint2*)g_whl)[i] = make_uint2(*(uint32_t*)&l0, *(uint32_t*)&l1);
    }
}

// ---------------- grouped GEMM: fp16 2-term (x * (Whi + Wlo)) ----------------
__global__ __launch_bounds__(256, 2)
void gemm_mma(const float* __restrict__ bias, float* __restrict__ out) {
    const int tile = blockIdx.x;
    const int e = g_tile_expert[tile];
    if (e < 0) return;
    const int rowbase = g_tile_rowbase[tile];
    const int rows    = g_tile_rows[tile];
    const int n0      = blockIdx.y * TN;

    extern __shared__ char sm[];
    int* srows = (int*)sm;
    const uint32_t smu = smem_u32(sm);

    const int tid  = threadIdx.x;
    const int lane = tid & 31;
    const int wid  = tid >> 5;

    if (tid < TM) srows[tid] = (tid < rows) ? g_rowidx[rowbase + tid] : -1;
    __syncthreads();

    // ---- cp.async slots ----
    // A: 128 rows x 4 sectors(16B) = 512 chunks -> 2/thread
    const __half* ag[2]; uint32_t asw[2];
#pragma unroll
    for (int t = 0; t < 2; t++) {
        int c = tid + t * 256;
        int m   = c >> 2;
        int sec = c & 3;
        int gr = srows[m]; if (gr < 0) gr = 0;
        ag[t]  = g_xh + (size_t)gr * DIN + sec * 8;
        asw[t] = OFF_BUF + AHI + m * (SA * 2) + sec * 16;
    }
    // B: 2 tensors x 32 k-rows x 16 sectors = 1024 chunks -> 4/thread
    const __half* bg[4]; uint32_t bsw[4];
#pragma unroll
    for (int t = 0; t < 4; t++) {
        int c = tid + t * 256;
        int tensor = c >> 9;
        int k   = (c >> 4) & 31;
        int sec = c & 15;
        bg[t]  = (tensor ? g_whl : g_whh)
               + ((size_t)e * DIN + k) * DOUT + n0 + sec * 8;
        bsw[t] = OFF_BUF + (tensor ? BLO : BHI) + k * (SB * 2) + sec * 16;
    }

    // ---- warp compute coords ----
    const int m0w = (wid >> 1) * 32;
    const int n0w = (wid & 1) * 64;
    const int lr = (lane & 7) + ((lane >> 3) & 1) * 8;
    const int lc = (lane >> 4) * 8;
    const int a_lm_base = ((m0w + lr) * SA + lc) * 2;
    const int b_lm_base = (lr * SB + n0w + lc) * 2;

    float c[2][8][4];
#pragma unroll
    for (int mt = 0; mt < 2; mt++)
#pragma unroll
        for (int nt = 0; nt < 8; nt++)
#pragma unroll
            for (int j = 0; j < 4; j++) c[mt][nt][j] = 0.f;

    // ---- prefetch stages 0 and 1 ----
#pragma unroll
    for (int s = 0; s < 2; s++) {
        const uint32_t bo = smu + s * BUF_BYTES;
        const int ka = s * TK;
        const size_t kb = (size_t)(s * TK) * DOUT;
#pragma unroll
        for (int t = 0; t < 2; t++) CP_ASYNC16(bo + asw[t], ag[t] + ka);
#pragma unroll
        for (int t = 0; t < 4; t++) CP_ASYNC16(bo + bsw[t], bg[t] + kb);
        CP_COMMIT();
    }

    for (int kt = 0; kt < NSTAGE; kt++) {
        if (kt < NSTAGE - 1) CP_WAIT(1); else CP_WAIT(0);
        __syncthreads();

        const int buf = kt & 1;
        const uint32_t bb = smu + OFF_BUF + buf * BUF_BYTES;

#pragma unroll
        for (int ks = 0; ks < 2; ks++) {
            const int kso = ks * 16;
            uint32_t ah[2][4];
#pragma unroll
            for (int mt = 0; mt < 2; mt++) {
                uint32_t ao = bb + a_lm_base + (mt * 16 * SA + kso) * 2;
                ldsm_x4(ah[mt], ao + AHI);
            }
            uint32_t bh[4][4], bl[4][4];
#pragma unroll
            for (int p = 0; p < 4; p++) {
                uint32_t bo = bb + b_lm_base + (kso * SB + p * 16) * 2;
                ldsm_x4_t(bh[p], bo + BHI);
                ldsm_x4_t(bl[p], bo + BLO);
            }
#pragma unroll
            for (int mt = 0; mt < 2; mt++)
#pragma unroll
                for (int p = 0; p < 4; p++) {
                    mma_f16(c[mt][2 * p],     ah[mt], &bh[p][0]);
                    mma_f16(c[mt][2 * p],     ah[mt], &bl[p][0]);
                    mma_f16(c[mt][2 * p + 1], ah[mt], &bh[p][2]);
                    mma_f16(c[mt][2 * p + 1], ah[mt], &bl[p][2]);
                }
        }

        __syncthreads();

        if (kt + 2 < NSTAGE) {
            const uint32_t bo = smu + buf * BUF_BYTES;
            const int ka = (kt + 2) * TK;
            const size_t kb = (size_t)((kt + 2) * TK) * DOUT;
#pragma unroll
            for (int t = 0; t < 2; t++) CP_ASYNC16(bo + asw[t], ag[t] + ka);
#pragma unroll
            for (int t = 0; t < 4; t++) CP_ASYNC16(bo + bsw[t], bg[t] + kb);
            CP_COMMIT();
        }
    }

    // ---- epilogue: bias + scattered stores ----
    const int rl = lane >> 2;
    const int cl = (lane & 3) * 2;
#pragma unroll
    for (int mt = 0; mt < 2; mt++) {
        const int lm0 = m0w + mt * 16 + rl;
        const int r0 = srows[lm0];
        const int r1 = srows[lm0 + 8];
#pragma unroll
        for (int nt = 0; nt < 8; nt++) {
            const int gcol = n0 + n0w + nt * 8 + cl;
            const float2 bv2 = *(const float2*)(bias + e * DOUT + gcol);
            if (r0 >= 0) {
                float2 v = make_float2(c[mt][nt][0] + bv2.x, c[mt][nt][1] + bv2.y);
                *(float2*)(out + (size_t)r0 * DOUT + gcol) = v;
            }
            if (r1 >= 0) {
                float2 v = make_float2(c[mt][nt][2] + bv2.x, c[mt][nt][3] + bv2.y);
                *(float2*)(out + (size_t)r1 * DOUT + gcol) = v;
            }
        }
    }
}

// ---------------- launch ----------------
extern "C" void kernel_launch(void* const* d_in, const int* in_sizes, int n_in,
                              void* d_out, int out_size) {
    const float* x      = (const float*)d_in[0];
    const int*   groups = (const int*)d_in[1];
    const float* W      = (const float*)d_in[2];
    const float* bias   = (const float*)d_in[3];
    float*       out    = (float*)d_out;

    cudaFuncSetAttribute(gemm_mma, cudaFuncAttributeMaxDynamicSharedMemorySize, GEMM_SMEM);

    reset_kernel<<<1, 32>>>();
    hist_kernel<<<64, 256>>>(groups);
    scan_kernel<<<1, 32>>>();
    scatter_kernel<<<B_ROWS / 256, 256>>>(groups);
    split_kernel<<<XBLOCKS + WBLOCKS, 256>>>(x, W);

    dim3 grid(MAXT, DOUT / TN);
    gemm_mma<<<grid, 256, GEMM_SMEM>>>(bias, out);
}

// round 6
// speedup vs baseline: 1.7975x; 1.3306x over previous
#include <cuda_runtime.h>
#include <cuda_fp16.h>
#include <cstdint>

// ---------------- problem constants ----------------
#define B_ROWS 16384
#define DIN 512
#define DOUT 512
#define NE 8
#define GCOLS 2

// ---------------- GEMM tiling ----------------
#define TM 128
#define TN 128
#define TK 32
#define NSTAGE (DIN / TK)          // 16
#define NPIPE 3
#define MAXT (B_ROWS / TM + NE)    // 136

#define SA 40    // A smem row stride (halves): 80B, conflict-free ldmatrix
#define SB 136   // B smem row stride (halves): 272B

// per-buffer smem offsets (bytes): A | B
#define AOF 0
#define BOF (TM * SA * 2)                     // 10240
#define BUF_BYTES (TM * SA * 2 + TK * SB * 2) // 18944
#define OFF_BUF 512
#define GEMM_SMEM (OFF_BUF + NPIPE * BUF_BYTES)  // 57344 -> 2 CTAs/SM

// ---------------- device scratch ----------------
__device__ int g_counts[NE];
__device__ int g_offsets[NE];
__device__ int g_fill[NE];
__device__ int g_rowidx[B_ROWS];
__device__ int g_tile_expert[MAXT];
__device__ int g_tile_rowbase[MAXT];
__device__ int g_tile_rows[MAXT];

__device__ __align__(16) __half g_xh[B_ROWS * DIN];      // 16MB
__device__ __align__(16) __half g_wh[NE * DIN * DOUT];   // 4MB, [e][k][n]

// ---------------- helpers ----------------
__device__ __forceinline__ uint32_t smem_u32(const void* p) {
    uint32_t a;
    asm("{ .reg .u64 t; cvta.to.shared.u64 t, %1; cvt.u32.u64 %0, t; }" : "=r"(a) : "l"(p));
    return a;
}
__device__ __forceinline__ void ldsm_x4(uint32_t* r, uint32_t addr) {
    asm volatile("ldmatrix.sync.aligned.m8n8.x4.shared.b16 {%0,%1,%2,%3}, [%4];"
                 : "=r"(r[0]), "=r"(r[1]), "=r"(r[2]), "=r"(r[3]) : "r"(addr));
}
__device__ __forceinline__ void ldsm_x4_t(uint32_t* r, uint32_t addr) {
    asm volatile("ldmatrix.sync.aligned.m8n8.x4.trans.shared.b16 {%0,%1,%2,%3}, [%4];"
                 : "=r"(r[0]), "=r"(r[1]), "=r"(r[2]), "=r"(r[3]) : "r"(addr));
}
__device__ __forceinline__ void mma_f16(float* c, const uint32_t* a, const uint32_t* b) {
    asm volatile(
        "mma.sync.aligned.m16n8k16.row.col.f32.f16.f16.f32 "
        "{%0,%1,%2,%3}, {%4,%5,%6,%7}, {%8,%9}, {%0,%1,%2,%3};"
        : "+f"(c[0]), "+f"(c[1]), "+f"(c[2]), "+f"(c[3])
        : "r"(a[0]), "r"(a[1]), "r"(a[2]), "r"(a[3]), "r"(b[0]), "r"(b[1]));
}
#define CP_ASYNC16(saddr, gaddr) \
    asm volatile("cp.async.cg.shared.global [%0], [%1], 16;" :: "r"(saddr), "l"(gaddr))
#define CP_COMMIT() asm volatile("cp.async.commit_group;")
#define CP_WAIT(n)  asm volatile("cp.async.wait_group %0;" :: "n"(n) : "memory")

// ---------------- bucketing ----------------
__global__ void reset_kernel() {
    int t = threadIdx.x;
    if (t < NE) { g_counts[t] = 0; g_fill[t] = 0; }
}

__global__ void hist_kernel(const int* __restrict__ groups) {
    __shared__ int s[NE];
    if (threadIdx.x < NE) s[threadIdx.x] = 0;
    __syncthreads();
    for (int b = blockIdx.x * blockDim.x + threadIdx.x; b < B_ROWS;
         b += gridDim.x * blockDim.x)
        atomicAdd(&s[groups[b * GCOLS]], 1);
    __syncthreads();
    if (threadIdx.x < NE) atomicAdd(&g_counts[threadIdx.x], s[threadIdx.x]);
}

__global__ void scan_kernel() {
    if (threadIdx.x == 0) {
        int total = 0, t = 0;
        for (int e = 0; e < NE; e++) {
            g_offsets[e] = total;
            int cnt = g_counts[e];
            for (int s = 0; s < cnt; s += TM) {
                g_tile_expert[t]  = e;
                g_tile_rowbase[t] = total + s;
                g_tile_rows[t]    = (cnt - s < TM) ? (cnt - s) : TM;
                t++;
            }
            total += cnt;
        }
        for (; t < MAXT; t++) g_tile_expert[t] = -1;
    }
}

__global__ void scatter_kernel(const int* __restrict__ groups) {
    int b = blockIdx.x * blockDim.x + threadIdx.x;
    int e = groups[b * GCOLS];
    int lane = threadIdx.x & 31;
    unsigned mask = __match_any_sync(0xffffffffu, e);
    int leader = __ffs(mask) - 1;
    int prefix = __popc(mask & ((1u << lane) - 1));
    int base = 0;
    if (lane == leader) base = atomicAdd(&g_fill[e], __popc(mask));
    base = __shfl_sync(0xffffffffu, base, leader);
    g_rowidx[g_offsets[e] + base + prefix] = b;
}

// ---------------- fused prep: x, W -> fp16 ----------------
#define XBLOCKS (B_ROWS * DIN / 4 / 256)       // 8192
#define WBLOCKS (NE * DIN * DOUT / 4 / 256)    // 2048
__global__ void cvt_kernel(const float* __restrict__ x, const float* __restrict__ W) {
    int bid = blockIdx.x;
    const float4* src;
    uint2* dst;
    int i;
    if (bid < XBLOCKS) {
        i = bid * blockDim.x + threadIdx.x;
        src = (const float4*)x;
        dst = (uint2*)g_xh;
    } else {
        i = (bid - XBLOCKS) * blockDim.x + threadIdx.x;
        src = (const float4*)W;
        dst = (uint2*)g_wh;
    }
    float4 v = src[i];
    __half2 h0 = __floats2half2_rn(v.x, v.y);
    __half2 h1 = __floats2half2_rn(v.z, v.w);
    dst[i] = make_uint2(*(uint32_t*)&h0, *(uint32_t*)&h1);
}

// ---------------- grouped GEMM: pure fp16, 3-stage cp.async pipeline ----------------
__global__ __launch_bounds__(256, 2)
void gemm_mma(const float* __restrict__ bias, float* __restrict__ out) {
    const int tile = blockIdx.x;
    const int e = g_tile_expert[tile];
    if (e < 0) return;
    const int rowbase = g_tile_rowbase[tile];
    const int rows    = g_tile_rows[tile];
    const int n0      = blockIdx.y * TN;

    extern __shared__ char sm[];
    int* srows = (int*)sm;
    const uint32_t smu = smem_u32(sm);

    const int tid  = threadIdx.x;
    const int lane = tid & 31;
    const int wid  = tid >> 5;

    if (tid < TM) srows[tid] = (tid < rows) ? g_rowidx[rowbase + tid] : -1;
    __syncthreads();

    // ---- cp.async slots ----
    // A: 128 rows x 4 sectors(16B) = 512 chunks -> 2/thread
    const __half* ag[2]; uint32_t asw[2];
#pragma unroll
    for (int t = 0; t < 2; t++) {
        int c = tid + t * 256;
        int m   = c >> 2;
        int sec = c & 3;
        int gr = srows[m]; if (gr < 0) gr = 0;
        ag[t]  = g_xh + (size_t)gr * DIN + sec * 8;
        asw[t] = OFF_BUF + AOF + m * (SA * 2) + sec * 16;
    }
    // B: 32 k-rows x 16 sectors = 512 chunks -> 2/thread
    const __half* bg[2]; uint32_t bsw[2];
#pragma unroll
    for (int t = 0; t < 2; t++) {
        int c = tid + t * 256;
        int k   = c >> 4;
        int sec = c & 15;
        bg[t]  = g_wh + ((size_t)e * DIN + k) * DOUT + n0 + sec * 8;
        bsw[t] = OFF_BUF + BOF + k * (SB * 2) + sec * 16;
    }

    // ---- warp compute coords ----
    const int m0w = (wid >> 1) * 32;
    const int n0w = (wid & 1) * 64;
    const int lr = (lane & 7) + ((lane >> 3) & 1) * 8;
    const int lc = (lane >> 4) * 8;
    const int a_lm_base = ((m0w + lr) * SA + lc) * 2;
    const int b_lm_base = (lr * SB + n0w + lc) * 2;

    float c[2][8][4];
#pragma unroll
    for (int mt = 0; mt < 2; mt++)
#pragma unroll
        for (int nt = 0; nt < 8; nt++)
#pragma unroll
            for (int j = 0; j < 4; j++) c[mt][nt][j] = 0.f;

    // ---- prefetch NPIPE stages ----
#pragma unroll
    for (int s = 0; s < NPIPE; s++) {
        const uint32_t bo = smu + s * BUF_BYTES;
        const int ka = s * TK;
        const size_t kb = (size_t)(s * TK) * DOUT;
#pragma unroll
        for (int t = 0; t < 2; t++) CP_ASYNC16(bo + asw[t], ag[t] + ka);
#pragma unroll
        for (int t = 0; t < 2; t++) CP_ASYNC16(bo + bsw[t], bg[t] + kb);
        CP_COMMIT();
    }

    int buf = 0;
    for (int kt = 0; kt < NSTAGE; kt++) {
        CP_WAIT(NPIPE - 1);
        __syncthreads();

        const uint32_t bb = smu + OFF_BUF + buf * BUF_BYTES;

#pragma unroll
        for (int ks = 0; ks < 2; ks++) {
            const int kso = ks * 16;
            uint32_t ah[2][4];
#pragma unroll
            for (int mt = 0; mt < 2; mt++)
                ldsm_x4(ah[mt], bb + a_lm_base + (mt * 16 * SA + kso) * 2 + AOF);
            uint32_t bh[4][4];
#pragma unroll
            for (int p = 0; p < 4; p++)
                ldsm_x4_t(bh[p], bb + b_lm_base + (kso * SB + p * 16) * 2 + BOF);
#pragma unroll
            for (int mt = 0; mt < 2; mt++)
#pragma unroll
                for (int p = 0; p < 4; p++) {
                    mma_f16(c[mt][2 * p],     ah[mt], &bh[p][0]);
                    mma_f16(c[mt][2 * p + 1], ah[mt], &bh[p][2]);
                }
        }

        __syncthreads();

        if (kt + NPIPE < NSTAGE) {
            const uint32_t bo = smu + buf * BUF_BYTES;
            const int ka = (kt + NPIPE) * TK;
            const size_t kb = (size_t)((kt + NPIPE) * TK) * DOUT;
#pragma unroll
            for (int t = 0; t < 2; t++) CP_ASYNC16(bo + asw[t], ag[t] + ka);
#pragma unroll
            for (int t = 0; t < 2; t++) CP_ASYNC16(bo + bsw[t], bg[t] + kb);
        }
        CP_COMMIT();   // unconditional: keeps wait_group accounting exact

        buf = (buf + 1 == NPIPE) ? 0 : buf + 1;
    }

    // ---- epilogue: bias + scattered stores ----
    const int rl = lane >> 2;
    const int cl = (lane & 3) * 2;
#pragma unroll
    for (int mt = 0; mt < 2; mt++) {
        const int lm0 = m0w + mt * 16 + rl;
        const int r0 = srows[lm0];
        const int r1 = srows[lm0 + 8];
#pragma unroll
        for (int nt = 0; nt < 8; nt++) {
            const int gcol = n0 + n0w + nt * 8 + cl;
            const float2 bv2 = *(const float2*)(bias + e * DOUT + gcol);
            if (r0 >= 0) {
                float2 v = make_float2(c[mt][nt][0] + bv2.x, c[mt][nt][1] + bv2.y);
                *(float2*)(out + (size_t)r0 * DOUT + gcol) = v;
            }
            if (r1 >= 0) {
                float2 v = make_float2(c[mt][nt][2] + bv2.x, c[mt][nt][3] + bv2.y);
                *(float2*)(out + (size_t)r1 * DOUT + gcol) = v;
            }
        }
    }
}

// ---------------- launch ----------------
extern "C" void kernel_launch(void* const* d_in, const int* in_sizes, int n_in,
                              void* d_out, int out_size) {
    const float* x      = (const float*)d_in[0];
    const int*   groups = (const int*)d_in[1];
    const float* W      = (const float*)d_in[2];
    const float* bias   = (const float*)d_in[3];
    float*       out    = (float*)d_out;

    cudaFuncSetAttribute(gemm_mma, cudaFuncAttributeMaxDynamicSharedMemorySize, GEMM_SMEM);

    reset_kernel<<<1, 32>>>();
    hist_kernel<<<64, 256>>>(groups);
    scan_kernel<<<1, 32>>>();
    scatter_kernel<<<B_ROWS / 256, 256>>>(groups);
    cvt_kernel<<<XBLOCKS + WBLOCKS, 256>>>(x, W);

    dim3 grid(MAXT, DOUT / TN);
    gemm_mma<<<grid, 256, GEMM_SMEM>>>(bias, out);
}

// round 7
// speedup vs baseline: 2.1736x; 1.2092x over previous
#include <cuda_runtime.h>
#include <cuda_fp16.h>
#include <cstdint>

// ---------------- problem constants ----------------
#define B_ROWS 16384
#define DIN 512
#define DOUT 512
#define NE 8
#define GCOLS 2

// ---------------- GEMM tiling ----------------
#define TM 128
#define TN 128
#define TK 32
#define NSTAGE (DIN / TK)          // 16
#define NPIPE 4

#define SA 40    // A smem row stride (halves): 80B, conflict-free ldmatrix
#define SB 136   // B smem row stride (halves): 272B

#define AOF 0
#define BOF (TM * SA * 2)                     // 10240
#define BUF_BYTES (TM * SA * 2 + TK * SB * 2) // 18944
#define OFF_BUF 1024
#define GEMM_SMEM (OFF_BUF + NPIPE * BUF_BYTES)  // 76800

#define GEMM_GRID 304   // 2 CTAs/SM x 152 SMs

// ---------------- device scratch ----------------
__device__ int g_fill[NE];
__device__ int g_work;
__device__ int g_rowpad[NE * B_ROWS];   // padded per-expert row lists

__device__ __align__(16) __half g_xh[B_ROWS * DIN];      // 16MB
__device__ __align__(16) __half g_wh[NE * DIN * DOUT];   // 4MB, [e][k][n]

// ---------------- helpers ----------------
__device__ __forceinline__ uint32_t smem_u32(const void* p) {
    uint32_t a;
    asm("{ .reg .u64 t; cvta.to.shared.u64 t, %1; cvt.u32.u64 %0, t; }" : "=r"(a) : "l"(p));
    return a;
}
__device__ __forceinline__ void ldsm_x4(uint32_t* r, uint32_t addr) {
    asm volatile("ldmatrix.sync.aligned.m8n8.x4.shared.b16 {%0,%1,%2,%3}, [%4];"
                 : "=r"(r[0]), "=r"(r[1]), "=r"(r[2]), "=r"(r[3]) : "r"(addr));
}
__device__ __forceinline__ void ldsm_x4_t(uint32_t* r, uint32_t addr) {
    asm volatile("ldmatrix.sync.aligned.m8n8.x4.trans.shared.b16 {%0,%1,%2,%3}, [%4];"
                 : "=r"(r[0]), "=r"(r[1]), "=r"(r[2]), "=r"(r[3]) : "r"(addr));
}
__device__ __forceinline__ void mma_f16(float* c, const uint32_t* a, const uint32_t* b) {
    asm volatile(
        "mma.sync.aligned.m16n8k16.row.col.f32.f16.f16.f32 "
        "{%0,%1,%2,%3}, {%4,%5,%6,%7}, {%8,%9}, {%0,%1,%2,%3};"
        : "+f"(c[0]), "+f"(c[1]), "+f"(c[2]), "+f"(c[3])
        : "r"(a[0]), "r"(a[1]), "r"(a[2]), "r"(a[3]), "r"(b[0]), "r"(b[1]));
}
#define CP_ASYNC16(saddr, gaddr) \
    asm volatile("cp.async.cg.shared.global [%0], [%1], 16;" :: "r"(saddr), "l"(gaddr))
#define CP_COMMIT() asm volatile("cp.async.commit_group;")
#define CP_WAIT(n)  asm volatile("cp.async.wait_group %0;" :: "n"(n) : "memory")

// ---------------- reset ----------------
__global__ void reset_kernel() {
    int t = threadIdx.x;
    if (t < NE) g_fill[t] = 0;
    if (t == NE) g_work = 0;
}

// ---------------- fused prep: cvt x, cvt W, scatter ----------------
#define XBLOCKS (B_ROWS * DIN / 4 / 256)       // 8192
#define WBLOCKS (NE * DIN * DOUT / 4 / 256)    // 2048
#define SBLOCKS (B_ROWS / 256)                 // 64
#define PREP_GRID (XBLOCKS + WBLOCKS + SBLOCKS)

__global__ void prep_kernel(const float* __restrict__ x, const float* __restrict__ W,
                            const int* __restrict__ groups) {
    int bid = blockIdx.x;
    if (bid < XBLOCKS + WBLOCKS) {
        const float4* src;
        uint2* dst;
        int i;
        if (bid < XBLOCKS) {
            i = bid * blockDim.x + threadIdx.x;
            src = (const float4*)x;
            dst = (uint2*)g_xh;
        } else {
            i = (bid - XBLOCKS) * blockDim.x + threadIdx.x;
            src = (const float4*)W;
            dst = (uint2*)g_wh;
        }
        float4 v = src[i];
        __half2 h0 = __floats2half2_rn(v.x, v.y);
        __half2 h1 = __floats2half2_rn(v.z, v.w);
        dst[i] = make_uint2(*(uint32_t*)&h0, *(uint32_t*)&h1);
    } else {
        // scatter: warp-aggregated counting sort into padded regions
        int b = (bid - XBLOCKS - WBLOCKS) * blockDim.x + threadIdx.x;
        int e = groups[b * GCOLS];
        int lane = threadIdx.x & 31;
        unsigned mask = __match_any_sync(0xffffffffu, e);
        int leader = __ffs(mask) - 1;
        int prefix = __popc(mask & ((1u << lane) - 1));
        int base = 0;
        if (lane == leader) base = atomicAdd(&g_fill[e], __popc(mask));
        base = __shfl_sync(0xffffffffu, base, leader);
        g_rowpad[e * B_ROWS + base + prefix] = b;
    }
}

// ---------------- persistent grouped GEMM: fp16, 4-stage pipeline ----------------
__global__ __launch_bounds__(256, 2)
void gemm_mma(const float* __restrict__ bias, float* __restrict__ out) {
    extern __shared__ char sm[];
    // control region: [0:4) work bcast, [16:52) cum tiles, [256:768) srows, buffers @OFF_BUF
    int* sm_w   = (int*)sm;
    int* s_cum  = (int*)(sm + 16);
    int* srows  = (int*)(sm + 256);
    const uint32_t smu = smem_u32(sm);

    const int tid  = threadIdx.x;
    const int lane = tid & 31;
    const int wid  = tid >> 5;

    // per-CTA tile table from counts
    if (tid == 0) {
        int c = 0;
        s_cum[0] = 0;
        for (int e = 0; e < NE; e++) {
            c += (g_fill[e] + TM - 1) / TM;
            s_cum[e + 1] = c;
        }
    }
    __syncthreads();
    const int nwork = s_cum[NE] * 4;

    // warp compute coords (tile-invariant)
    const int m0w = (wid >> 1) * 32;
    const int n0w = (wid & 1) * 64;
    const int lr = (lane & 7) + ((lane >> 3) & 1) * 8;
    const int lc = (lane >> 4) * 8;
    const int a_lm_base = ((m0w + lr) * SA + lc) * 2;
    const int b_lm_base = (lr * SB + n0w + lc) * 2;

    // A cp.async slot shape (row source varies per tile)
    const int am0  = (tid + 0)   >> 2;          // row handled by slot 0
    const int am1  = (tid + 256) >> 2;          // row handled by slot 1
    const int asec0 = tid & 3;
    const uint32_t asw0 = smu + OFF_BUF + AOF + am0 * (SA * 2) + asec0 * 16;
    const uint32_t asw1 = smu + OFF_BUF + AOF + am1 * (SA * 2) + asec0 * 16;
    // B slot shape
    const int bk0 = (tid + 0) >> 4, bk1 = (tid + 256) >> 4;
    const int bsec = tid & 15;
    const uint32_t bsw0 = smu + OFF_BUF + BOF + bk0 * (SB * 2) + bsec * 16;
    const uint32_t bsw1 = smu + OFF_BUF + BOF + bk1 * (SB * 2) + bsec * 16;

    const int rl = lane >> 2;
    const int cl = (lane & 3) * 2;

    for (;;) {
        if (tid == 0) sm_w[0] = atomicAdd(&g_work, 1);
        __syncthreads();                        // also fences prev tile's smem reads
        const int w = sm_w[0];
        if (w >= nwork) break;

        // decode dense work id -> (expert, row base, col tile)
        const int n0 = (w & 3) * TN;
        const int t  = w >> 2;
        int e = 0;
        while (t >= s_cum[e + 1]) e++;
        const int rowbase = (t - s_cum[e]) * TM;
        const int cnt  = g_fill[e];
        const int rows = (cnt - rowbase < TM) ? (cnt - rowbase) : TM;

        if (tid < TM) srows[tid] = (tid < rows) ? g_rowpad[e * B_ROWS + rowbase + tid] : -1;
        __syncthreads();

        // per-tile global pointers
        int gr0 = srows[am0]; if (gr0 < 0) gr0 = 0;
        int gr1 = srows[am1]; if (gr1 < 0) gr1 = 0;
        const __half* ag0 = g_xh + (size_t)gr0 * DIN + asec0 * 8;
        const __half* ag1 = g_xh + (size_t)gr1 * DIN + asec0 * 8;
        const __half* bg0 = g_wh + ((size_t)e * DIN + bk0) * DOUT + n0 + bsec * 8;
        const __half* bg1 = g_wh + ((size_t)e * DIN + bk1) * DOUT + n0 + bsec * 8;

        float c[2][8][4];
#pragma unroll
        for (int mt = 0; mt < 2; mt++)
#pragma unroll
            for (int nt = 0; nt < 8; nt++)
#pragma unroll
                for (int j = 0; j < 4; j++) c[mt][nt][j] = 0.f;

        // prologue: stages 0..2
#pragma unroll
        for (int s = 0; s < NPIPE - 1; s++) {
            const uint32_t bo = s * BUF_BYTES;
            const int ka = s * TK;
            const size_t kb = (size_t)(s * TK) * DOUT;
            CP_ASYNC16(asw0 + bo, ag0 + ka);
            CP_ASYNC16(asw1 + bo, ag1 + ka);
            CP_ASYNC16(bsw0 + bo, bg0 + kb);
            CP_ASYNC16(bsw1 + bo, bg1 + kb);
            CP_COMMIT();
        }

        // mainloop: one barrier per stage
        for (int kt = 0; kt < NSTAGE; kt++) {
            CP_WAIT(NPIPE - 2);
            __syncthreads();

            if (kt + NPIPE - 1 < NSTAGE) {
                const int sl = (kt + NPIPE - 1) & (NPIPE - 1);
                const uint32_t bo = sl * BUF_BYTES;
                const int ka = (kt + NPIPE - 1) * TK;
                const size_t kb = (size_t)((kt + NPIPE - 1) * TK) * DOUT;
                CP_ASYNC16(asw0 + bo, ag0 + ka);
                CP_ASYNC16(asw1 + bo, ag1 + ka);
                CP_ASYNC16(bsw0 + bo, bg0 + kb);
                CP_ASYNC16(bsw1 + bo, bg1 + kb);
            }
            CP_COMMIT();

            const uint32_t bb = smu + OFF_BUF + (kt & (NPIPE - 1)) * BUF_BYTES;
#pragma unroll
            for (int ks = 0; ks < 2; ks++) {
                const int kso = ks * 16;
                uint32_t ah[2][4];
#pragma unroll
                for (int mt = 0; mt < 2; mt++)
                    ldsm_x4(ah[mt], bb + a_lm_base + (mt * 16 * SA + kso) * 2 + AOF);
                uint32_t bh[4][4];
#pragma unroll
                for (int p = 0; p < 4; p++)
                    ldsm_x4_t(bh[p], bb + b_lm_base + (kso * SB + p * 16) * 2 + BOF);
#pragma unroll
                for (int mt = 0; mt < 2; mt++)
#pragma unroll
                    for (int p = 0; p < 4; p++) {
                        mma_f16(c[mt][2 * p],     ah[mt], &bh[p][0]);
                        mma_f16(c[mt][2 * p + 1], ah[mt], &bh[p][2]);
                    }
            }
        }

        // epilogue: bias + scattered stores
#pragma unroll
        for (int mt = 0; mt < 2; mt++) {
            const int lm0 = m0w + mt * 16 + rl;
            const int r0 = srows[lm0];
            const int r1 = srows[lm0 + 8];
#pragma unroll
            for (int nt = 0; nt < 8; nt++) {
                const int gcol = n0 + n0w + nt * 8 + cl;
                const float2 bv2 = *(const float2*)(bias + e * DOUT + gcol);
                if (r0 >= 0) {
                    float2 v = make_float2(c[mt][nt][0] + bv2.x, c[mt][nt][1] + bv2.y);
                    *(float2*)(out + (size_t)r0 * DOUT + gcol) = v;
                }
                if (r1 >= 0) {
                    float2 v = make_float2(c[mt][nt][2] + bv2.x, c[mt][nt][3] + bv2.y);
                    *(float2*)(out + (size_t)r1 * DOUT + gcol) = v;
                }
            }
        }
    }
}

// ---------------- launch ----------------
extern "C" void kernel_launch(void* const* d_in, const int* in_sizes, int n_in,
                              void* d_out, int out_size) {
    const float* x      = (const float*)d_in[0];
    const int*   groups = (const int*)d_in[1];
    const float* W      = (const float*)d_in[2];
    const float* bias   = (const float*)d_in[3];
    float*       out    = (float*)d_out;

    cudaFuncSetAttribute(gemm_mma, cudaFuncAttributeMaxDynamicSharedMemorySize, GEMM_SMEM);

    reset_kernel<<<1, 32>>>();
    prep_kernel<<<PREP_GRID, 256>>>(x, W, groups);
    gemm_mma<<<GEMM_GRID, 256, GEMM_SMEM>>>(bias, out);
}